// round 15
// baseline (speedup 1.0000x reference)
#include <cuda_runtime.h>
#include <math.h>

#define NB 1024
#define NC 100000
#define THREADS 256

// scratch: per-row NLL
static __device__ float g_nll[NB];

__device__ __forceinline__ float ex2_fast(float x) {
    float y;
    asm("ex2.approx.ftz.f32 %0, %1;" : "=f"(y) : "f"(x));
    return y;
}

// 64 * log2(e)
#define K2 92.33248261625200f
#define LOG2E 1.4426950408889634f

__device__ __forceinline__ float term(float v) {
    float c = fminf(fmaxf(v, -1.0f), 1.0f);
    return ex2_fast(fmaf(c, K2, -K2));   // exp(64*c - 64)
}

__global__ void __launch_bounds__(THREADS)
row_lse_kernel(const float* __restrict__ x,
               const int* __restrict__ label,
               const float* __restrict__ margin) {
    const int row = blockIdx.x;
    const float4* __restrict__ p =
        reinterpret_cast<const float4*>(x + (size_t)row * NC);
    const int n4 = NC / 4;  // 25000

    const int lane = threadIdx.x & 31;
    const int wid  = threadIdx.x >> 5;

    // ---- hoisted epilogue precompute (lane 0 of warp 0 only) ----
    // The dependent target gather + MUFU trig chain overlaps the stream
    // instead of sitting on the block's tail after the reduction.
    float e_orig = 0.0f, e_mod = 0.0f, l_mod = 0.0f;
    if (threadIdx.x == 0) {
        int lb = __ldg(label + row);
        const bool valid = (lb >= 0);
        int tgt = valid ? lb : 0;
        tgt = min(max(tgt, 0), NC - 1);       // never fabricate OOB address
        const float mg = valid ? __ldg(margin + row) : 0.0f;

        float xt = __ldg(x + (size_t)row * NC + tgt);
        float c  = fminf(fmaxf(xt, -1.0f), 1.0f);
        l_mod  = 64.0f * cosf(acosf(c) + mg);
        e_orig = ex2_fast(fmaf(c, K2, -K2));
        e_mod  = ex2_fast((l_mod - 64.0f) * LOG2E);
    }

    // ---- streaming exp-sum (proven champion loop) ----
    float s0 = 0.0f, s1 = 0.0f, s2 = 0.0f, s3 = 0.0f;
    #pragma unroll 8
    for (int i = threadIdx.x; i < n4; i += THREADS) {
        float4 v = __ldcs(p + i);
        s0 += term(v.x);
        s1 += term(v.y);
        s2 += term(v.z);
        s3 += term(v.w);
    }
    float s = (s0 + s1) + (s2 + s3);

    // block reduction
    __shared__ float red[THREADS / 32];
    #pragma unroll
    for (int o = 16; o; o >>= 1) s += __shfl_xor_sync(0xFFFFFFFFu, s, o);
    if (lane == 0) red[wid] = s;
    __syncthreads();

    if (wid == 0) {
        float t = (lane < THREADS / 32) ? red[lane] : 0.0f;
        #pragma unroll
        for (int o = (THREADS / 64); o; o >>= 1)
            t += __shfl_xor_sync(0xFFFFFFFFu, t, o);

        if (lane == 0) {
            // replace target term: subtract original, add modified
            float stot = t - e_orig + e_mod;
            // nll = lse - l_mod,  lse = 64 + log(stot)
            g_nll[row] = 64.0f + logf(stot) - l_mod;
        }
    }
}

// single-warp mean: 32 threads x 8 float4 = 1024 floats, MLP=8 pipelined
__global__ void __launch_bounds__(32)
mean_kernel(float* __restrict__ out) {
    const int lane = threadIdx.x;
    const float4* __restrict__ p = reinterpret_cast<const float4*>(g_nll);

    float s = 0.0f;
    #pragma unroll
    for (int k = 0; k < 8; k++) {
        float4 v = p[lane + 32 * k];           // 256 float4 total
        s += (v.x + v.y) + (v.z + v.w);
    }
    #pragma unroll
    for (int o = 16; o; o >>= 1) s += __shfl_xor_sync(0xFFFFFFFFu, s, o);
    if (lane == 0) out[0] = s * (1.0f / (float)NB);
}

extern "C" void kernel_launch(void* const* d_in, const int* in_sizes, int n_in,
                              void* d_out, int out_size) {
    const float* x      = (const float*)d_in[0];
    const int*   label  = (const int*)d_in[1];
    const float* margin = (const float*)d_in[2];
    float*       out    = (float*)d_out;

    row_lse_kernel<<<NB, THREADS>>>(x, label, margin);
    mean_kernel<<<1, 32>>>(out);
}

// round 16
// speedup vs baseline: 1.0312x; 1.0312x over previous
#include <cuda_runtime.h>
#include <math.h>

#define NB 1024
#define NC 100000
#define THREADS 256

// scratch: per-row NLL
static __device__ float g_nll[NB];

__device__ __forceinline__ float ex2_fast(float x) {
    float y;
    asm("ex2.approx.ftz.f32 %0, %1;" : "=f"(y) : "f"(x));
    return y;
}

// 64 * log2(e)
#define K2 92.33248261625200f
#define LOG2E 1.4426950408889634f

__device__ __forceinline__ float term(float v) {
    float c = fminf(fmaxf(v, -1.0f), 1.0f);
    return ex2_fast(fmaf(c, K2, -K2));   // exp(64*c - 64)
}

__global__ void __launch_bounds__(THREADS)
row_lse_kernel(const float* __restrict__ x,
               const int* __restrict__ label,
               const float* __restrict__ margin) {
    const int row = blockIdx.x;
    const float4* __restrict__ p =
        reinterpret_cast<const float4*>(x + (size_t)row * NC);
    const int n4 = NC / 4;  // 25000

    // 4 independent accumulators: breaks the serial FADD chain on s
    float s0 = 0.0f, s1 = 0.0f, s2 = 0.0f, s3 = 0.0f;
    #pragma unroll 8
    for (int i = threadIdx.x; i < n4; i += THREADS) {
        float4 v = __ldcs(p + i);
        s0 += term(v.x);
        s1 += term(v.y);
        s2 += term(v.z);
        s3 += term(v.w);
    }
    float s = (s0 + s1) + (s2 + s3);

    // block reduction
    __shared__ float red[THREADS / 32];
    const int lane = threadIdx.x & 31;
    const int wid  = threadIdx.x >> 5;
    #pragma unroll
    for (int o = 16; o; o >>= 1) s += __shfl_xor_sync(0xFFFFFFFFu, s, o);
    if (lane == 0) red[wid] = s;
    __syncthreads();

    if (wid == 0) {
        float t = (lane < THREADS / 32) ? red[lane] : 0.0f;
        #pragma unroll
        for (int o = (THREADS / 64); o; o >>= 1)
            t += __shfl_xor_sync(0xFFFFFFFFu, t, o);

        if (lane == 0) {
            int lb = __ldg(label + row);
            const bool valid = (lb >= 0);
            int tgt = valid ? lb : 0;
            tgt = min(max(tgt, 0), NC - 1);   // never fabricate OOB address
            const float mg = valid ? __ldg(margin + row) : 0.0f;

            float xt = __ldg(x + (size_t)row * NC + tgt);
            float c  = fminf(fmaxf(xt, -1.0f), 1.0f);
            float l_mod = 64.0f * cosf(acosf(c) + mg);

            // replace target term: subtract original, add modified
            float stot = t - ex2_fast(fmaf(c, K2, -K2))
                           + ex2_fast((l_mod - 64.0f) * LOG2E);

            // nll = lse - l_mod,  lse = 64 + log(stot)
            g_nll[row] = 64.0f + logf(stot) - l_mod;
        }
    }
}

// single-warp mean: 32 threads x 8 float4 = 1024 floats, MLP=8 pipelined
__global__ void __launch_bounds__(32)
mean_kernel(float* __restrict__ out) {
    const int lane = threadIdx.x;
    const float4* __restrict__ p = reinterpret_cast<const float4*>(g_nll);

    float s = 0.0f;
    #pragma unroll
    for (int k = 0; k < 8; k++) {
        float4 v = p[lane + 32 * k];           // 256 float4 total
        s += (v.x + v.y) + (v.z + v.w);
    }
    #pragma unroll
    for (int o = 16; o; o >>= 1) s += __shfl_xor_sync(0xFFFFFFFFu, s, o);
    if (lane == 0) out[0] = s * (1.0f / (float)NB);
}

extern "C" void kernel_launch(void* const* d_in, const int* in_sizes, int n_in,
                              void* d_out, int out_size) {
    const float* x      = (const float*)d_in[0];
    const int*   label  = (const int*)d_in[1];
    const float* margin = (const float*)d_in[2];
    float*       out    = (float*)d_out;

    row_lse_kernel<<<NB, THREADS>>>(x, label, margin);
    mean_kernel<<<1, 32>>>(out);
}